// round 2
// baseline (speedup 1.0000x reference)
#include <cuda_runtime.h>
#include <math.h>

#define NPER 20000
#define CH 64
#define NREL 15
#define NEDGE 30000
#define NH 60000

__constant__ int c_tsrc[NREL] = {0,1,2,0,1,2,0,1,2,0,0,1,1,2,2};
__constant__ int c_tdst[NREL] = {0,1,2,0,1,2,0,1,2,1,2,0,2,0,1};
__constant__ int c_off[3] = {0, 2*NPER, NPER};

// ---------------- scratch (device globals; no allocs allowed) ----------------
__device__ float    g_hs[(size_t)NREL*NPER*CH];
__device__ float    g_as[NREL*NPER];
__device__ float    g_ad[NREL*NPER];
__device__ float    g_cnt[NREL*NPER];
__device__ float    g_icnt[NREL*NPER];
__device__ float    g_acc[3*NPER*CH];      // per-layer scatter target
__device__ float    g_xd[3*NPER*CH];       // layer-1 output (type-major)
__device__ float    g_hx[3*NPER*CH];       // layer-2 output (attention row order)
__device__ float    g_u0[6*CH];
__device__ float    g_cd[6];
__device__ float    g_q[(size_t)NH*128];
__device__ float    g_k[(size_t)NH*128];
__device__ float    g_v[(size_t)NH*128];
__device__ float    g_outb[(size_t)NH*CH];
__device__ float    g_score[(size_t)NREL*NEDGE*2];
__device__ unsigned g_smax[NH*2];
__device__ float    g_den[NH*2];
__device__ float    g_num[(size_t)NH*128];
__device__ double   g_sum[CH];
__device__ double   g_sumsq[CH];
__device__ float    g_mu[CH];
__device__ float    g_rstd[CH];

__device__ __forceinline__ void red_add_v4(float* p, float4 v) {
    asm volatile("red.global.add.v4.f32 [%0], {%1,%2,%3,%4};"
                 :: "l"(p), "f"(v.x), "f"(v.y), "f"(v.z), "f"(v.w) : "memory");
}

// ---------------- edge counts (static across layers) -------------------------
__global__ void cnt_kernel(const int* __restrict__ ei) {
    int e = blockIdx.x*blockDim.x + threadIdx.x;
    if (e >= NREL*NEDGE) return;
    int r = e / NEDGE, w = e - r*NEDGE;
    int dst = ei[(size_t)r*2*NEDGE + NEDGE + w];
    atomicAdd(&g_cnt[r*NPER + dst], 1.0f);
}
__global__ void icnt_kernel() {
    int i = blockIdx.x*blockDim.x + threadIdx.x;
    if (i < NREL*NPER) g_icnt[i] = 0.2f / fmaxf(g_cnt[i], 1.0f);
}

// ---------------- prep: u0 = Wlin @ wa0, cd = blin . wa0 (cross relations) ---
__global__ void prep_u_kernel(const float* __restrict__ Wlin_l,
                              const float* __restrict__ blin_l,
                              const float* __restrict__ Wa_l) {
    int k = threadIdx.x; // 64
    for (int j = 0; j < 6; j++) {
        int r = 9 + j;
        const float* W = Wlin_l + r*4096 + k*64;
        const float* wa0 = Wa_l + r*128;
        float s = 0.f;
        #pragma unroll 8
        for (int c = 0; c < 64; c++) s += W[c] * wa0[c];
        g_u0[j*64 + k] = s;
    }
    if (k < 6) {
        int r = 9 + k;
        float s = 0.f;
        for (int c = 0; c < 64; c++) s += blin_l[r*64 + c] * Wa_l[r*128 + c];
        g_cd[k] = s;
    }
}

// ---------------- hs = x[tsrc] @ Wlin + blin ; fused a_s / a_d ---------------
// 64-row tiles, 256 threads, 2 rows x 8 cols per thread.
__global__ void lin_kernel(const float* __restrict__ x,
                           const float* __restrict__ Wlin_l,
                           const float* __restrict__ blin_l,
                           const float* __restrict__ Wa_l,
                           const float* __restrict__ ba_l) {
    __shared__ __align__(16) float Ws[4096];
    __shared__ float xs[64*65];
    __shared__ float wa0s[64], wa1s[64], bsh[64];
    int r = blockIdx.y;
    int tid = threadIdx.x;
    const float* W = Wlin_l + r*4096;
    for (int i = tid; i < 4096; i += 256) Ws[i] = W[i];
    if (tid < 64) {
        wa0s[tid] = Wa_l[r*128 + tid];
        wa1s[tid] = Wa_l[r*128 + 64 + tid];
        bsh[tid]  = blin_l[r*64 + tid];
    }
    int t = c_tsrc[r];
    int row0 = blockIdx.x*64;
    int nrows = NPER - row0; if (nrows > 64) nrows = 64;
    const float* xb = x + ((size_t)t*NPER + row0)*CH;
    for (int i = tid; i < 1024; i += 256) {
        int rr = i >> 4, c4 = i & 15;
        float4 v = (rr < nrows) ? ((const float4*)xb)[rr*16 + c4]
                                : make_float4(0.f,0.f,0.f,0.f);
        float* d = &xs[rr*65 + c4*4];
        d[0]=v.x; d[1]=v.y; d[2]=v.z; d[3]=v.w;
    }
    __syncthreads();

    int rr = tid >> 3, cg = tid & 7;
    float acc0[8], acc1[8];
    #pragma unroll
    for (int j = 0; j < 8; j++) { acc0[j] = bsh[cg*8+j]; acc1[j] = acc0[j]; }
    const float4* Ws4 = (const float4*)Ws;
    #pragma unroll 8
    for (int k = 0; k < 64; k++) {
        float x0 = xs[rr*65 + k];
        float x1 = xs[(rr+32)*65 + k];
        float4 w0 = Ws4[k*16 + cg*2];
        float4 w1 = Ws4[k*16 + cg*2 + 1];
        acc0[0]+=x0*w0.x; acc0[1]+=x0*w0.y; acc0[2]+=x0*w0.z; acc0[3]+=x0*w0.w;
        acc0[4]+=x0*w1.x; acc0[5]+=x0*w1.y; acc0[6]+=x0*w1.z; acc0[7]+=x0*w1.w;
        acc1[0]+=x1*w0.x; acc1[1]+=x1*w0.y; acc1[2]+=x1*w0.z; acc1[3]+=x1*w0.w;
        acc1[4]+=x1*w1.x; acc1[5]+=x1*w1.y; acc1[6]+=x1*w1.z; acc1[7]+=x1*w1.w;
    }
    float ba = ba_l[r];
    #pragma unroll
    for (int half = 0; half < 2; half++) {
        float* acc = half ? acc1 : acc0;
        int n = row0 + rr + half*32;
        float asp = 0.f, adp = 0.f;
        #pragma unroll
        for (int j = 0; j < 8; j++) {
            int c = cg*8 + j;
            asp += acc[j] * wa1s[c];
            adp += acc[j] * wa0s[c];
        }
        #pragma unroll
        for (int s = 4; s; s >>= 1) {
            asp += __shfl_xor_sync(0xffffffffu, asp, s);
            adp += __shfl_xor_sync(0xffffffffu, adp, s);
        }
        if (n < NPER) {
            float* hsrow = g_hs + ((size_t)r*NPER + n)*CH + cg*8;
            ((float4*)hsrow)[0] = make_float4(acc[0],acc[1],acc[2],acc[3]);
            ((float4*)hsrow)[1] = make_float4(acc[4],acc[5],acc[6],acc[7]);
            if (cg == 0) {
                g_as[r*NPER + n] = asp;
                if (r < 9) g_ad[r*NPER + n] = adp + ba;   // tsrc==tdst
            }
        }
    }
}

// ---------------- a_d for the 6 cross-type relations -------------------------
__global__ void ad_cross_kernel(const float* __restrict__ x,
                                const float* __restrict__ ba_l) {
    int j = blockIdx.y;
    int r = 9 + j;
    int warp = threadIdx.x >> 5, lane = threadIdx.x & 31;
    int n = blockIdx.x*8 + warp;
    int t = c_tdst[r];
    const float* xrow = x + ((size_t)t*NPER + n)*CH;
    float p = xrow[lane]*g_u0[j*64 + lane] + xrow[lane+32]*g_u0[j*64 + lane + 32];
    #pragma unroll
    for (int s = 16; s; s >>= 1) p += __shfl_xor_sync(0xffffffffu, p, s);
    if (lane == 0) g_ad[r*NPER + n] = p + g_cd[j] + ba_l[r];
}

// ---------------- per-edge gated message scatter (direct to type accum) ------
__global__ void edge_scatter_kernel(const int* __restrict__ ei) {
    int idx = blockIdx.x*blockDim.x + threadIdx.x;
    int e = idx >> 4, lane = idx & 15;
    if (e >= NREL*NEDGE) return;
    int r = e / NEDGE, w = e - r*NEDGE;
    const int* base = ei + (size_t)r*2*NEDGE;
    int src = base[w], dst = base[NEDGE + w];
    float g = 0.f;
    if (lane == 0)
        g = tanhf(g_ad[r*NPER + dst] + g_as[r*NPER + src]) * g_icnt[r*NPER + dst];
    g = __shfl_sync(0xffffffffu, g, threadIdx.x & 16);
    float4 h = ((const float4*)(g_hs + ((size_t)r*NPER + src)*CH))[lane];
    int t = c_tdst[r];
    red_add_v4(g_acc + ((size_t)t*NPER + dst)*CH + lane*4,
               make_float4(g*h.x, g*h.y, g*h.z, g*h.w));
}

// ---------------- relu + store layer output ----------------------------------
// mode 0: row = t*NPER+n (type-major, feeds layer 2)
// mode 1: row = OFF[t]+n  (attention hx order, feeds qkv)
__global__ void relu_kernel(int mode, float* __restrict__ dst) {
    int idx = blockIdx.x*blockDim.x + threadIdx.x;  // 3*NPER*16
    if (idx >= 3*NPER*16) return;
    int lane = idx & 15, tn = idx >> 4;
    int t = tn / NPER, n = tn - t*NPER;
    float4 a = ((const float4*)(g_acc + (size_t)tn*CH))[lane];
    a.x = fmaxf(a.x, 0.f); a.y = fmaxf(a.y, 0.f);
    a.z = fmaxf(a.z, 0.f); a.w = fmaxf(a.w, 0.f);
    int row = mode ? (c_off[t] + n) : tn;
    ((float4*)(dst + (size_t)row*CH))[lane] = a;
}

// ---------------- q/k/v/skip GEMM (7 chunks of 64 cols) ----------------------
__global__ void qkv_kernel(const float* __restrict__ Wq, const float* __restrict__ bq,
                           const float* __restrict__ Wk, const float* __restrict__ bk,
                           const float* __restrict__ Wv, const float* __restrict__ bv,
                           const float* __restrict__ Wskip, const float* __restrict__ bskip) {
    __shared__ __align__(16) float Ws[4096];
    __shared__ float xs[64*65];
    __shared__ float bsh[64];
    int chunk = blockIdx.y;
    const float *Wsrc, *bsrc;
    float* dst;
    int ldW, coff, ldD;
    if (chunk < 2)      { Wsrc = Wq;    bsrc = bq;    dst = g_q;    ldW = 128; coff = chunk*64;     ldD = 128; }
    else if (chunk < 4) { Wsrc = Wk;    bsrc = bk;    dst = g_k;    ldW = 128; coff = (chunk-2)*64; ldD = 128; }
    else if (chunk < 6) { Wsrc = Wv;    bsrc = bv;    dst = g_v;    ldW = 128; coff = (chunk-4)*64; ldD = 128; }
    else                { Wsrc = Wskip; bsrc = bskip; dst = g_outb; ldW = 64;  coff = 0;            ldD = 64;  }
    int tid = threadIdx.x;
    for (int i = tid; i < 4096; i += 256) Ws[i] = Wsrc[(i>>6)*ldW + coff + (i&63)];
    if (tid < 64) bsh[tid] = bsrc[coff + tid];
    int m0 = blockIdx.x*64;
    int nrows = NH - m0; if (nrows > 64) nrows = 64;
    const float* xb = g_hx + (size_t)m0*CH;
    for (int i = tid; i < 1024; i += 256) {
        int rr = i >> 4, c4 = i & 15;
        float4 v = (rr < nrows) ? ((const float4*)xb)[rr*16 + c4]
                                : make_float4(0.f,0.f,0.f,0.f);
        float* d = &xs[rr*65 + c4*4];
        d[0]=v.x; d[1]=v.y; d[2]=v.z; d[3]=v.w;
    }
    __syncthreads();

    int rr = tid >> 3, cg = tid & 7;
    float acc0[8], acc1[8];
    #pragma unroll
    for (int j = 0; j < 8; j++) { acc0[j] = bsh[cg*8+j]; acc1[j] = acc0[j]; }
    const float4* Ws4 = (const float4*)Ws;
    #pragma unroll 8
    for (int k = 0; k < 64; k++) {
        float x0 = xs[rr*65 + k];
        float x1 = xs[(rr+32)*65 + k];
        float4 w0 = Ws4[k*16 + cg*2];
        float4 w1 = Ws4[k*16 + cg*2 + 1];
        acc0[0]+=x0*w0.x; acc0[1]+=x0*w0.y; acc0[2]+=x0*w0.z; acc0[3]+=x0*w0.w;
        acc0[4]+=x0*w1.x; acc0[5]+=x0*w1.y; acc0[6]+=x0*w1.z; acc0[7]+=x0*w1.w;
        acc1[0]+=x1*w0.x; acc1[1]+=x1*w0.y; acc1[2]+=x1*w0.z; acc1[3]+=x1*w0.w;
        acc1[4]+=x1*w1.x; acc1[5]+=x1*w1.y; acc1[6]+=x1*w1.z; acc1[7]+=x1*w1.w;
    }
    #pragma unroll
    for (int half = 0; half < 2; half++) {
        float* acc = half ? acc1 : acc0;
        int m = m0 + rr + half*32;
        if (m < NH) {
            float* drow = dst + (size_t)m*ldD + coff + cg*8;
            ((float4*)drow)[0] = make_float4(acc[0],acc[1],acc[2],acc[3]);
            ((float4*)drow)[1] = make_float4(acc[4],acc[5],acc[6],acc[7]);
        }
    }
}

// ---------------- attention scores + segment max -----------------------------
__global__ void score_kernel(const int* __restrict__ ei) {
    int gw = (blockIdx.x*blockDim.x + threadIdx.x) >> 5;
    int lane = threadIdx.x & 31;
    if (gw >= NREL*NEDGE) return;
    int r = gw / NEDGE, w = gw - r*NEDGE;
    const int* base = ei + (size_t)r*2*NEDGE;
    int hsrc = base[w] + c_off[c_tsrc[r]];
    int hdst = base[NEDGE + w] + c_off[c_tdst[r]];
    int h = lane >> 4, l4 = lane & 15;
    float4 a = ((const float4*)(g_q + (size_t)hdst*128 + h*64))[l4];
    float4 b = ((const float4*)(g_k + (size_t)hsrc*128 + h*64))[l4];
    float p = a.x*b.x + a.y*b.y + a.z*b.z + a.w*b.w;
    p += __shfl_xor_sync(0xffffffffu, p, 8);
    p += __shfl_xor_sync(0xffffffffu, p, 4);
    p += __shfl_xor_sync(0xffffffffu, p, 2);
    p += __shfl_xor_sync(0xffffffffu, p, 1);
    if (l4 == 0) {
        float s = p * 0.125f;
        g_score[(size_t)gw*2 + h] = s;
        unsigned u = __float_as_uint(s);
        unsigned key = (u & 0x80000000u) ? ~u : (u | 0x80000000u);
        atomicMax(&g_smax[hdst*2 + h], key);
    }
}

// ---------------- attention exp + weighted-v scatter -------------------------
__global__ void attn_kernel(const int* __restrict__ ei) {
    int gw = (blockIdx.x*blockDim.x + threadIdx.x) >> 5;
    int lane = threadIdx.x & 31;
    if (gw >= NREL*NEDGE) return;
    int r = gw / NEDGE, w = gw - r*NEDGE;
    const int* base = ei + (size_t)r*2*NEDGE;
    int hsrc = base[w] + c_off[c_tsrc[r]];
    int hdst = base[NEDGE + w] + c_off[c_tdst[r]];
    int h = lane >> 4, l4 = lane & 15;
    float s = g_score[(size_t)gw*2 + h];
    unsigned key = g_smax[hdst*2 + h];
    float m = (key & 0x80000000u) ? __uint_as_float(key ^ 0x80000000u)
                                  : __uint_as_float(~key);
    float a = __expf(s - m);
    float4 v = ((const float4*)(g_v + (size_t)hsrc*128 + h*64))[l4];
    red_add_v4(g_num + (size_t)hdst*128 + h*64 + l4*4,
               make_float4(a*v.x, a*v.y, a*v.z, a*v.w));
    if (l4 == 0) atomicAdd(&g_den[hdst*2 + h], a);
}

// ---------------- finalize rows + channel stats ------------------------------
__global__ void reduce_kernel() {
    int c = threadIdx.x & 63;
    int sub = threadIdx.x >> 6;
    int base = blockIdx.x * 256;
    double s = 0.0, s2 = 0.0;
    for (int i = 0; i < 64; i++) {
        int m = base + sub*64 + i;
        if (m < NH) {
            float d0 = g_den[m*2]     + 1e-16f;
            float d1 = g_den[m*2 + 1] + 1e-16f;
            float val = g_outb[(size_t)m*64 + c]
                      + 0.5f * (g_num[(size_t)m*128 + c] / d0
                              + g_num[(size_t)m*128 + 64 + c] / d1);
            g_outb[(size_t)m*64 + c] = val;
            s += val;
            s2 += (double)val * (double)val;
        }
    }
    __shared__ double ss[256], sq[256];
    ss[threadIdx.x] = s; sq[threadIdx.x] = s2;
    __syncthreads();
    if (threadIdx.x < 64) {
        double ts = ss[threadIdx.x] + ss[threadIdx.x+64] + ss[threadIdx.x+128] + ss[threadIdx.x+192];
        double tq = sq[threadIdx.x] + sq[threadIdx.x+64] + sq[threadIdx.x+128] + sq[threadIdx.x+192];
        atomicAdd(&g_sum[c], ts);
        atomicAdd(&g_sumsq[c], tq);
    }
}

__global__ void stats_kernel() {
    int c = threadIdx.x;
    double mu = g_sum[c] / (double)NH;
    double var = g_sumsq[c] / (double)NH - mu*mu;
    g_mu[c] = (float)mu;
    g_rstd[c] = rsqrtf((float)var + 1e-5f);
}

// ---------------- layernorm + leaky relu + permuted output -------------------
__global__ void final_kernel(const float* __restrict__ gamma,
                             const float* __restrict__ beta,
                             float* __restrict__ out) {
    int idx = blockIdx.x*blockDim.x + threadIdx.x;
    if (idx >= 3*NPER*CH) return;
    int c = idx & 63;
    int rown = idx >> 6;
    int b = rown / NPER, n = rown - b*NPER;
    int srow = (b == 0) ? n : ((b == 1) ? (2*NPER + n) : (NPER + n));
    float v = g_outb[(size_t)srow*CH + c];
    v = gamma[c] * (v - g_mu[c]) * g_rstd[c] + beta[c];
    out[idx] = (v >= 0.f) ? v : 0.01f * v;
}

// ---------------- host orchestration -----------------------------------------
extern "C" void kernel_launch(void* const* d_in, const int* in_sizes, int n_in,
                              void* d_out, int out_size) {
    const float* x     = (const float*)d_in[0];
    const int*   ei    = (const int*)  d_in[1];
    const float* Wlin  = (const float*)d_in[2];
    const float* blin  = (const float*)d_in[3];
    const float* Wa    = (const float*)d_in[4];
    const float* ba    = (const float*)d_in[5];
    const float* Wq    = (const float*)d_in[6];
    const float* bq    = (const float*)d_in[7];
    const float* Wk    = (const float*)d_in[8];
    const float* bk    = (const float*)d_in[9];
    const float* Wv    = (const float*)d_in[10];
    const float* bv    = (const float*)d_in[11];
    const float* Wskip = (const float*)d_in[12];
    const float* bskip = (const float*)d_in[13];
    const float* gamma = (const float*)d_in[14];
    const float* beta  = (const float*)d_in[15];
    float* out = (float*)d_out;

    void *p_cnt, *p_acc, *p_num, *p_den, *p_smax, *p_sum, *p_sumsq, *p_xd, *p_hx;
    cudaGetSymbolAddress(&p_cnt, g_cnt);
    cudaGetSymbolAddress(&p_acc, g_acc);
    cudaGetSymbolAddress(&p_num, g_num);
    cudaGetSymbolAddress(&p_den, g_den);
    cudaGetSymbolAddress(&p_smax, g_smax);
    cudaGetSymbolAddress(&p_sum, g_sum);
    cudaGetSymbolAddress(&p_sumsq, g_sumsq);
    cudaGetSymbolAddress(&p_xd, g_xd);
    cudaGetSymbolAddress(&p_hx, g_hx);

    // edge counts: static across both layers
    cudaMemsetAsync(p_cnt, 0, sizeof(float)*NREL*NPER);
    cnt_kernel<<<(NREL*NEDGE + 255)/256, 256>>>(ei);
    icnt_kernel<<<(NREL*NPER + 255)/256, 256>>>();

    for (int l = 0; l < 2; l++) {
        const float* xin = (l == 0) ? x : (const float*)p_xd;
        const float* Wlin_l = Wlin + (size_t)l*NREL*4096;
        const float* blin_l = blin + (size_t)l*NREL*64;
        const float* Wa_l   = Wa   + (size_t)l*NREL*128;
        const float* ba_l   = ba   + (size_t)l*NREL;
        prep_u_kernel<<<1, 64>>>(Wlin_l, blin_l, Wa_l);
        lin_kernel<<<dim3(313, 15), 256>>>(xin, Wlin_l, blin_l, Wa_l, ba_l);
        ad_cross_kernel<<<dim3(2500, 6), 256>>>(xin, ba_l);
        cudaMemsetAsync(p_acc, 0, sizeof(float)*3*NPER*CH);
        edge_scatter_kernel<<<28125, 256>>>(ei);
        relu_kernel<<<(3*NPER*16 + 255)/256, 256>>>(l, l == 0 ? (float*)p_xd : (float*)p_hx);
    }
    cudaMemsetAsync(p_num, 0, sizeof(float)*(size_t)NH*128);
    cudaMemsetAsync(p_den, 0, sizeof(float)*NH*2);
    cudaMemsetAsync(p_smax, 0, sizeof(unsigned)*NH*2);
    cudaMemsetAsync(p_sum, 0, sizeof(double)*CH);
    cudaMemsetAsync(p_sumsq, 0, sizeof(double)*CH);

    qkv_kernel<<<dim3(938, 7), 256>>>(Wq, bq, Wk, bk, Wv, bv, Wskip, bskip);
    score_kernel<<<56250, 256>>>(ei);
    attn_kernel<<<56250, 256>>>(ei);
    reduce_kernel<<<235, 256>>>();
    stats_kernel<<<1, 64>>>();
    final_kernel<<<15000, 256>>>(gamma, beta, out);
}

// round 3
// speedup vs baseline: 2.2997x; 2.2997x over previous
#include <cuda_runtime.h>
#include <math.h>

#define NPER 20000
#define CH 64
#define NREL 15
#define NEDGE 30000
#define NH 60000

__constant__ int c_tsrc[NREL] = {0,1,2,0,1,2,0,1,2,0,0,1,1,2,2};
__constant__ int c_tdst[NREL] = {0,1,2,0,1,2,0,1,2,1,2,0,2,0,1};
__constant__ int c_off[3] = {0, 2*NPER, NPER};

// ---------------- scratch (device globals; no allocs allowed) ----------------
__device__ float    g_hs[(size_t)NREL*NPER*CH];
__device__ float    g_as[NREL*NPER];
__device__ float    g_ad[NREL*NPER];
__device__ float    g_cnt[NREL*NPER];
__device__ float    g_icnt[NREL*NPER];
__device__ float    g_acc[3*NPER*CH];
__device__ float    g_xd[3*NPER*CH];       // layer-1 output (type-major)
__device__ float    g_hx[3*NPER*CH];       // layer-2 output (attention row order)
__device__ float    g_u0[6*CH];
__device__ float    g_cd[6];
__device__ float    g_q[(size_t)NH*128];
__device__ float    g_k[(size_t)NH*128];
__device__ float    g_v[(size_t)NH*128];
__device__ float    g_outb[(size_t)NH*CH];
__device__ float    g_score[(size_t)NREL*NEDGE*2];
__device__ unsigned g_smax[NH*2];
__device__ float    g_den[NH*2];
__device__ float    g_num[(size_t)NH*128];
__device__ double   g_sum[CH];
__device__ double   g_sumsq[CH];
__device__ float    g_mu[CH];
__device__ float    g_rstd[CH];

__device__ __forceinline__ void red_add_v4(float* p, float4 v) {
    asm volatile("red.global.add.v4.f32 [%0], {%1,%2,%3,%4};"
                 :: "l"(p), "f"(v.x), "f"(v.y), "f"(v.z), "f"(v.w) : "memory");
}
__device__ __forceinline__ unsigned f2tf(float f) {
    unsigned u; asm("cvt.rna.tf32.f32 %0, %1;" : "=r"(u) : "f"(f)); return u;
}
__device__ __forceinline__ void mma_tf32(float c[4], unsigned a0, unsigned a1,
                                         unsigned a2, unsigned a3,
                                         unsigned b0, unsigned b1) {
    asm volatile("mma.sync.aligned.m16n8k8.row.col.f32.tf32.tf32.f32 "
                 "{%0,%1,%2,%3}, {%4,%5,%6,%7}, {%8,%9}, {%0,%1,%2,%3};"
                 : "+f"(c[0]), "+f"(c[1]), "+f"(c[2]), "+f"(c[3])
                 : "r"(a0), "r"(a1), "r"(a2), "r"(a3), "r"(b0), "r"(b1));
}

// ---------------- edge counts (static across layers) -------------------------
__global__ void cnt_kernel(const int* __restrict__ ei) {
    int e = blockIdx.x*blockDim.x + threadIdx.x;
    if (e >= NREL*NEDGE) return;
    int r = e / NEDGE, w = e - r*NEDGE;
    int dst = ei[(size_t)r*2*NEDGE + NEDGE + w];
    atomicAdd(&g_cnt[r*NPER + dst], 1.0f);
}
__global__ void icnt_kernel() {
    int i = blockIdx.x*blockDim.x + threadIdx.x;
    if (i < NREL*NPER) g_icnt[i] = 0.2f / fmaxf(g_cnt[i], 1.0f);
}

// ---------------- prep: u0 = Wlin @ wa0, cd = blin . wa0 (cross relations) ---
__global__ void prep_u_kernel(const float* __restrict__ Wlin_l,
                              const float* __restrict__ blin_l,
                              const float* __restrict__ Wa_l) {
    int k = threadIdx.x; // 64
    for (int j = 0; j < 6; j++) {
        int r = 9 + j;
        const float* W = Wlin_l + r*4096 + k*64;
        const float* wa0 = Wa_l + r*128;
        float s = 0.f;
        #pragma unroll 8
        for (int c = 0; c < 64; c++) s += W[c] * wa0[c];
        g_u0[j*64 + k] = s;
    }
    if (k < 6) {
        int r = 9 + k;
        float s = 0.f;
        for (int c = 0; c < 64; c++) s += blin_l[r*64 + c] * Wa_l[r*128 + c];
        g_cd[k] = s;
    }
}

// ---------------- hs = x[tsrc] @ Wlin + blin  (tf32 tensor-core MMA) ---------
// 64-row tile, 256 threads = 8 warps: 4 row-groups x 2 col-halves.
__global__ void lin_mma_kernel(const float* __restrict__ x,
                               const float* __restrict__ Wlin_l,
                               const float* __restrict__ blin_l) {
    __shared__ unsigned xs[64][68];
    __shared__ unsigned Ws[64][68];
    __shared__ float bsh[64];
    int r = blockIdx.y;
    int tid = threadIdx.x;
    const float* W = Wlin_l + r*4096;
    for (int i = tid; i < 1024; i += 256) {
        float4 v = ((const float4*)W)[i];
        int rr = i >> 4, c4 = (i & 15)*4;
        Ws[rr][c4+0] = f2tf(v.x); Ws[rr][c4+1] = f2tf(v.y);
        Ws[rr][c4+2] = f2tf(v.z); Ws[rr][c4+3] = f2tf(v.w);
    }
    if (tid < 64) bsh[tid] = blin_l[r*64 + tid];
    int t = c_tsrc[r];
    int row0 = blockIdx.x*64;
    const float* xb = x + ((size_t)t*NPER + row0)*CH;
    for (int i = tid; i < 1024; i += 256) {
        int rr = i >> 4, c4 = (i & 15)*4;
        float4 v = (row0 + rr < NPER) ? ((const float4*)xb)[i]
                                      : make_float4(0.f,0.f,0.f,0.f);
        xs[rr][c4+0] = f2tf(v.x); xs[rr][c4+1] = f2tf(v.y);
        xs[rr][c4+2] = f2tf(v.z); xs[rr][c4+3] = f2tf(v.w);
    }
    __syncthreads();

    int warp = tid >> 5, lane = tid & 31;
    int wr = warp >> 1, wc = warp & 1;
    int gid = lane >> 2, tig = lane & 3;
    int rA = wr*16 + gid;
    float acc[4][4];
    #pragma unroll
    for (int nt = 0; nt < 4; nt++)
        #pragma unroll
        for (int j = 0; j < 4; j++) acc[nt][j] = 0.f;

    #pragma unroll
    for (int kk = 0; kk < 8; kk++) {
        int k0 = kk*8;
        unsigned a0 = xs[rA][k0+tig],   a1 = xs[rA+8][k0+tig];
        unsigned a2 = xs[rA][k0+tig+4], a3 = xs[rA+8][k0+tig+4];
        #pragma unroll
        for (int nt = 0; nt < 4; nt++) {
            int n0 = wc*32 + nt*8 + gid;
            mma_tf32(acc[nt], a0, a1, a2, a3, Ws[k0+tig][n0], Ws[k0+tig+4][n0]);
        }
    }
    int n = row0 + rA;
    float* base = g_hs + ((size_t)r*NPER + n)*CH;
    #pragma unroll
    for (int nt = 0; nt < 4; nt++) {
        int col = wc*32 + nt*8 + 2*tig;
        if (n < NPER)
            *(float2*)(base + col) = make_float2(acc[nt][0]+bsh[col], acc[nt][1]+bsh[col+1]);
        if (n + 8 < NPER)
            *(float2*)(base + 8*CH + col) = make_float2(acc[nt][2]+bsh[col], acc[nt][3]+bsh[col+1]);
    }
}

// ---------------- a_s (all r) and a_d (r<9) dots from hs ---------------------
__global__ void as_kernel(const float* __restrict__ Wa_l,
                          const float* __restrict__ ba_l) {
    int gw = (blockIdx.x*blockDim.x + threadIdx.x) >> 5;
    int lane = threadIdx.x & 31;
    if (gw >= NREL*NPER) return;
    int r = gw / NPER;
    float2 h  = ((const float2*)(g_hs + (size_t)gw*CH))[lane];
    float2 w1 = ((const float2*)(Wa_l + r*128 + 64))[lane];
    float2 w0 = ((const float2*)(Wa_l + r*128))[lane];
    float s = h.x*w1.x + h.y*w1.y;
    float d = h.x*w0.x + h.y*w0.y;
    #pragma unroll
    for (int o = 16; o; o >>= 1) {
        s += __shfl_xor_sync(0xffffffffu, s, o);
        d += __shfl_xor_sync(0xffffffffu, d, o);
    }
    if (lane == 0) {
        g_as[gw] = s;
        if (r < 9) g_ad[gw] = d + ba_l[r];
    }
}

// ---------------- a_d for the 6 cross-type relations -------------------------
__global__ void ad_cross_kernel(const float* __restrict__ x,
                                const float* __restrict__ ba_l) {
    int j = blockIdx.y;
    int r = 9 + j;
    int warp = threadIdx.x >> 5, lane = threadIdx.x & 31;
    int n = blockIdx.x*8 + warp;
    int t = c_tdst[r];
    const float* xrow = x + ((size_t)t*NPER + n)*CH;
    float p = xrow[lane]*g_u0[j*64 + lane] + xrow[lane+32]*g_u0[j*64 + lane + 32];
    #pragma unroll
    for (int s = 16; s; s >>= 1) p += __shfl_xor_sync(0xffffffffu, p, s);
    if (lane == 0) g_ad[r*NPER + n] = p + g_cd[j] + ba_l[r];
}

// ---------------- per-edge gated message scatter (direct to type accum) ------
__global__ void edge_scatter_kernel(const int* __restrict__ ei) {
    int idx = blockIdx.x*blockDim.x + threadIdx.x;
    int e = idx >> 4, lane = idx & 15;
    if (e >= NREL*NEDGE) return;
    int r = e / NEDGE, w = e - r*NEDGE;
    const int* base = ei + (size_t)r*2*NEDGE;
    int src = base[w], dst = base[NEDGE + w];
    float g = 0.f;
    if (lane == 0)
        g = tanhf(g_ad[r*NPER + dst] + g_as[r*NPER + src]) * g_icnt[r*NPER + dst];
    g = __shfl_sync(0xffffffffu, g, threadIdx.x & 16);
    float4 h = ((const float4*)(g_hs + ((size_t)r*NPER + src)*CH))[lane];
    int t = c_tdst[r];
    red_add_v4(g_acc + ((size_t)t*NPER + dst)*CH + lane*4,
               make_float4(g*h.x, g*h.y, g*h.z, g*h.w));
}

// ---------------- relu + store layer output ----------------------------------
__global__ void relu_kernel(int mode, float* __restrict__ dst) {
    int idx = blockIdx.x*blockDim.x + threadIdx.x;
    if (idx >= 3*NPER*16) return;
    int lane = idx & 15, tn = idx >> 4;
    int t = tn / NPER, n = tn - t*NPER;
    float4 a = ((const float4*)(g_acc + (size_t)tn*CH))[lane];
    a.x = fmaxf(a.x, 0.f); a.y = fmaxf(a.y, 0.f);
    a.z = fmaxf(a.z, 0.f); a.w = fmaxf(a.w, 0.f);
    int row = mode ? (c_off[t] + n) : tn;
    ((float4*)(dst + (size_t)row*CH))[lane] = a;
}

// ---------------- q/k/v/skip GEMM via tf32 MMA (7 chunks of 64 cols) ---------
__global__ void qkv_mma_kernel(const float* __restrict__ Wq, const float* __restrict__ bq,
                               const float* __restrict__ Wk, const float* __restrict__ bk,
                               const float* __restrict__ Wv, const float* __restrict__ bv,
                               const float* __restrict__ Wskip, const float* __restrict__ bskip) {
    __shared__ unsigned xs[64][68];
    __shared__ unsigned Ws[64][68];
    __shared__ float bsh[64];
    int chunk = blockIdx.y;
    const float *Wsrc, *bsrc;
    float* dst;
    int ldW, coff, ldD;
    if (chunk < 2)      { Wsrc = Wq;    bsrc = bq;    dst = g_q;    ldW = 128; coff = chunk*64;     ldD = 128; }
    else if (chunk < 4) { Wsrc = Wk;    bsrc = bk;    dst = g_k;    ldW = 128; coff = (chunk-2)*64; ldD = 128; }
    else if (chunk < 6) { Wsrc = Wv;    bsrc = bv;    dst = g_v;    ldW = 128; coff = (chunk-4)*64; ldD = 128; }
    else                { Wsrc = Wskip; bsrc = bskip; dst = g_outb; ldW = 64;  coff = 0;            ldD = 64;  }
    int tid = threadIdx.x;
    for (int i = tid; i < 4096; i += 256)
        Ws[i>>6][i&63] = f2tf(Wsrc[(i>>6)*ldW + coff + (i&63)]);
    if (tid < 64) bsh[tid] = bsrc[coff + tid];
    int m0 = blockIdx.x*64;
    const float* xb = g_hx + (size_t)m0*CH;
    for (int i = tid; i < 1024; i += 256) {
        int rr = i >> 4, c4 = (i & 15)*4;
        float4 v = (m0 + rr < NH) ? ((const float4*)xb)[i]
                                  : make_float4(0.f,0.f,0.f,0.f);
        xs[rr][c4+0] = f2tf(v.x); xs[rr][c4+1] = f2tf(v.y);
        xs[rr][c4+2] = f2tf(v.z); xs[rr][c4+3] = f2tf(v.w);
    }
    __syncthreads();

    int warp = tid >> 5, lane = tid & 31;
    int wr = warp >> 1, wc = warp & 1;
    int gid = lane >> 2, tig = lane & 3;
    int rA = wr*16 + gid;
    float acc[4][4];
    #pragma unroll
    for (int nt = 0; nt < 4; nt++)
        #pragma unroll
        for (int j = 0; j < 4; j++) acc[nt][j] = 0.f;

    #pragma unroll
    for (int kk = 0; kk < 8; kk++) {
        int k0 = kk*8;
        unsigned a0 = xs[rA][k0+tig],   a1 = xs[rA+8][k0+tig];
        unsigned a2 = xs[rA][k0+tig+4], a3 = xs[rA+8][k0+tig+4];
        #pragma unroll
        for (int nt = 0; nt < 4; nt++) {
            int n0 = wc*32 + nt*8 + gid;
            mma_tf32(acc[nt], a0, a1, a2, a3, Ws[k0+tig][n0], Ws[k0+tig+4][n0]);
        }
    }
    int m = m0 + rA;
    #pragma unroll
    for (int nt = 0; nt < 4; nt++) {
        int col = wc*32 + nt*8 + 2*tig;
        if (m < NH)
            *(float2*)(dst + (size_t)m*ldD + coff + col)
                = make_float2(acc[nt][0]+bsh[col], acc[nt][1]+bsh[col+1]);
        if (m + 8 < NH)
            *(float2*)(dst + (size_t)(m+8)*ldD + coff + col)
                = make_float2(acc[nt][2]+bsh[col], acc[nt][3]+bsh[col+1]);
    }
}

// ---------------- attention scores + segment max -----------------------------
__global__ void score_kernel(const int* __restrict__ ei) {
    int gw = (blockIdx.x*blockDim.x + threadIdx.x) >> 5;
    int lane = threadIdx.x & 31;
    if (gw >= NREL*NEDGE) return;
    int r = gw / NEDGE, w = gw - r*NEDGE;
    const int* base = ei + (size_t)r*2*NEDGE;
    int hsrc = base[w] + c_off[c_tsrc[r]];
    int hdst = base[NEDGE + w] + c_off[c_tdst[r]];
    int h = lane >> 4, l4 = lane & 15;
    float4 a = ((const float4*)(g_q + (size_t)hdst*128 + h*64))[l4];
    float4 b = ((const float4*)(g_k + (size_t)hsrc*128 + h*64))[l4];
    float p = a.x*b.x + a.y*b.y + a.z*b.z + a.w*b.w;
    p += __shfl_xor_sync(0xffffffffu, p, 8);
    p += __shfl_xor_sync(0xffffffffu, p, 4);
    p += __shfl_xor_sync(0xffffffffu, p, 2);
    p += __shfl_xor_sync(0xffffffffu, p, 1);
    if (l4 == 0) {
        float s = p * 0.125f;
        g_score[(size_t)gw*2 + h] = s;
        unsigned u = __float_as_uint(s);
        unsigned key = (u & 0x80000000u) ? ~u : (u | 0x80000000u);
        atomicMax(&g_smax[hdst*2 + h], key);
    }
}

// ---------------- attention exp + weighted-v scatter -------------------------
__global__ void attn_kernel(const int* __restrict__ ei) {
    int gw = (blockIdx.x*blockDim.x + threadIdx.x) >> 5;
    int lane = threadIdx.x & 31;
    if (gw >= NREL*NEDGE) return;
    int r = gw / NEDGE, w = gw - r*NEDGE;
    const int* base = ei + (size_t)r*2*NEDGE;
    int hsrc = base[w] + c_off[c_tsrc[r]];
    int hdst = base[NEDGE + w] + c_off[c_tdst[r]];
    int h = lane >> 4, l4 = lane & 15;
    float s = g_score[(size_t)gw*2 + h];
    unsigned key = g_smax[hdst*2 + h];
    float m = (key & 0x80000000u) ? __uint_as_float(key ^ 0x80000000u)
                                  : __uint_as_float(~key);
    float a = __expf(s - m);
    float4 v = ((const float4*)(g_v + (size_t)hsrc*128 + h*64))[l4];
    red_add_v4(g_num + (size_t)hdst*128 + h*64 + l4*4,
               make_float4(a*v.x, a*v.y, a*v.z, a*v.w));
    if (l4 == 0) atomicAdd(&g_den[hdst*2 + h], a);
}

// ---------------- finalize rows + channel stats ------------------------------
__global__ void reduce_kernel() {
    int c = threadIdx.x & 63;
    int sub = threadIdx.x >> 6;
    int base = blockIdx.x * 256;
    double s = 0.0, s2 = 0.0;
    for (int i = 0; i < 64; i++) {
        int m = base + sub*64 + i;
        if (m < NH) {
            float d0 = g_den[m*2]     + 1e-16f;
            float d1 = g_den[m*2 + 1] + 1e-16f;
            float val = g_outb[(size_t)m*64 + c]
                      + 0.5f * (g_num[(size_t)m*128 + c] / d0
                              + g_num[(size_t)m*128 + 64 + c] / d1);
            g_outb[(size_t)m*64 + c] = val;
            s += val;
            s2 += (double)val * (double)val;
        }
    }
    __shared__ double ss[256], sq[256];
    ss[threadIdx.x] = s; sq[threadIdx.x] = s2;
    __syncthreads();
    if (threadIdx.x < 64) {
        double ts = ss[threadIdx.x] + ss[threadIdx.x+64] + ss[threadIdx.x+128] + ss[threadIdx.x+192];
        double tq = sq[threadIdx.x] + sq[threadIdx.x+64] + sq[threadIdx.x+128] + sq[threadIdx.x+192];
        atomicAdd(&g_sum[c], ts);
        atomicAdd(&g_sumsq[c], tq);
    }
}

__global__ void stats_kernel() {
    int c = threadIdx.x;
    double mu = g_sum[c] / (double)NH;
    double var = g_sumsq[c] / (double)NH - mu*mu;
    g_mu[c] = (float)mu;
    g_rstd[c] = rsqrtf((float)var + 1e-5f);
}

// ---------------- layernorm + leaky relu + permuted output -------------------
__global__ void final_kernel(const float* __restrict__ gamma,
                             const float* __restrict__ beta,
                             float* __restrict__ out) {
    int idx = blockIdx.x*blockDim.x + threadIdx.x;
    if (idx >= 3*NPER*CH) return;
    int c = idx & 63;
    int rown = idx >> 6;
    int b = rown / NPER, n = rown - b*NPER;
    int srow = (b == 0) ? n : ((b == 1) ? (2*NPER + n) : (NPER + n));
    float v = g_outb[(size_t)srow*CH + c];
    v = gamma[c] * (v - g_mu[c]) * g_rstd[c] + beta[c];
    out[idx] = (v >= 0.f) ? v : 0.01f * v;
}

// ---------------- host orchestration -----------------------------------------
extern "C" void kernel_launch(void* const* d_in, const int* in_sizes, int n_in,
                              void* d_out, int out_size) {
    const float* x     = (const float*)d_in[0];
    const int*   ei    = (const int*)  d_in[1];
    const float* Wlin  = (const float*)d_in[2];
    const float* blin  = (const float*)d_in[3];
    const float* Wa    = (const float*)d_in[4];
    const float* ba    = (const float*)d_in[5];
    const float* Wq    = (const float*)d_in[6];
    const float* bq    = (const float*)d_in[7];
    const float* Wk    = (const float*)d_in[8];
    const float* bk    = (const float*)d_in[9];
    const float* Wv    = (const float*)d_in[10];
    const float* bv    = (const float*)d_in[11];
    const float* Wskip = (const float*)d_in[12];
    const float* bskip = (const float*)d_in[13];
    const float* gamma = (const float*)d_in[14];
    const float* beta  = (const float*)d_in[15];
    float* out = (float*)d_out;

    void *p_cnt, *p_acc, *p_num, *p_den, *p_smax, *p_sum, *p_sumsq, *p_xd, *p_hx;
    cudaGetSymbolAddress(&p_cnt, g_cnt);
    cudaGetSymbolAddress(&p_acc, g_acc);
    cudaGetSymbolAddress(&p_num, g_num);
    cudaGetSymbolAddress(&p_den, g_den);
    cudaGetSymbolAddress(&p_smax, g_smax);
    cudaGetSymbolAddress(&p_sum, g_sum);
    cudaGetSymbolAddress(&p_sumsq, g_sumsq);
    cudaGetSymbolAddress(&p_xd, g_xd);
    cudaGetSymbolAddress(&p_hx, g_hx);

    cudaMemsetAsync(p_cnt, 0, sizeof(float)*NREL*NPER);
    cnt_kernel<<<(NREL*NEDGE + 255)/256, 256>>>(ei);
    icnt_kernel<<<(NREL*NPER + 255)/256, 256>>>();

    for (int l = 0; l < 2; l++) {
        const float* xin = (l == 0) ? x : (const float*)p_xd;
        const float* Wlin_l = Wlin + (size_t)l*NREL*4096;
        const float* blin_l = blin + (size_t)l*NREL*64;
        const float* Wa_l   = Wa   + (size_t)l*NREL*128;
        const float* ba_l   = ba   + (size_t)l*NREL;
        prep_u_kernel<<<1, 64>>>(Wlin_l, blin_l, Wa_l);
        lin_mma_kernel<<<dim3(313, 15), 256>>>(xin, Wlin_l, blin_l);
        as_kernel<<<37500, 256>>>(Wa_l, ba_l);
        ad_cross_kernel<<<dim3(2500, 6), 256>>>(xin, ba_l);
        cudaMemsetAsync(p_acc, 0, sizeof(float)*3*NPER*CH);
        edge_scatter_kernel<<<28125, 256>>>(ei);
        relu_kernel<<<(3*NPER*16 + 255)/256, 256>>>(l, l == 0 ? (float*)p_xd : (float*)p_hx);
    }
    cudaMemsetAsync(p_num, 0, sizeof(float)*(size_t)NH*128);
    cudaMemsetAsync(p_den, 0, sizeof(float)*NH*2);
    cudaMemsetAsync(p_smax, 0, sizeof(unsigned)*NH*2);
    cudaMemsetAsync(p_sum, 0, sizeof(double)*CH);
    cudaMemsetAsync(p_sumsq, 0, sizeof(double)*CH);

    qkv_mma_kernel<<<dim3(938, 7), 256>>>(Wq, bq, Wk, bk, Wv, bv, Wskip, bskip);
    score_kernel<<<56250, 256>>>(ei);
    attn_kernel<<<56250, 256>>>(ei);
    reduce_kernel<<<235, 256>>>();
    stats_kernel<<<1, 64>>>();
    final_kernel<<<15000, 256>>>(gamma, beta, out);
}